// round 2
// baseline (speedup 1.0000x reference)
#include <cuda_runtime.h>
#include <math.h>

#define B_DIM  512
#define IN_DIM 64
#define H_DIM  256
#define T_DIM  200
#define O_DIM  2
#define NBLK   128
#define NTHR   256
#define BN_EPS 1e-5f

// output region offsets (floats)
#define Y_OFF   0
#define HID_OFF (B_DIM*T_DIM*O_DIM)                     // 204800
#define X_OFF   (HID_OFF + B_DIM*T_DIM*H_DIM)           // 26419200
#define M_OFF   (X_OFF + B_DIM*IN_DIM*T_DIM)            // 32972800

// ---------------- device scratch (static globals: allocation-free) ----------
__device__ float g_xt[B_DIM*IN_DIM*T_DIM];   // [t][b][i]
__device__ float g_mt[B_DIM*IN_DIM*T_DIM];
__device__ float g_dt[B_DIM*IN_DIM*T_DIM];
__device__ float g_h[B_DIM*H_DIM];           // normalized hidden carry
__device__ float g_hg[B_DIM*H_DIM];          // gamma_h * h
__device__ float g_hnew[B_DIM*H_DIM];        // pre-BN hidden
__device__ float g_rh[B_DIM*H_DIM];          // r * hg
__device__ float g_ximp[B_DIM*IN_DIM];
__device__ float g_xlast[B_DIM*IN_DIM];
__device__ float g_bnsum[2][H_DIM];
__device__ float g_bnsq[2][H_DIM];
__device__ unsigned int g_bar_count;
__device__ unsigned int g_bar_gen;

// ---------------- grid barrier --------------------------------------------
__device__ __forceinline__ void grid_sync() {
    __syncthreads();
    if (threadIdx.x == 0) {
        volatile unsigned int* genp = (volatile unsigned int*)&g_bar_gen;
        unsigned int gen = *genp;
        __threadfence();
        if (atomicAdd(&g_bar_count, 1u) == (unsigned)(NBLK - 1)) {
            g_bar_count = 0u;
            __threadfence();
            *genp = gen + 1u;
        } else {
            while (*genp == gen) { __nanosleep(20); }
        }
        __threadfence();
    }
    __syncthreads();
}

__device__ __forceinline__ float sigm(float v) { return 1.0f / (1.0f + expf(-v)); }

#define LD4(p) (*(const float4*)(p))

// two-gate GEMM segment: acc{a,b}[2x2] += sT(k,row) * w{1,2}(col,k)
__device__ __forceinline__ void seg2(
    const float* __restrict__ w1, const float* __restrict__ w2, int ld, int kmax,
    int c0, int c1, const float* __restrict__ sT, int r0, int r1,
    float& a00, float& a01, float& a10, float& a11,
    float& b00, float& b01, float& b10, float& b11)
{
    for (int k4 = 0; k4 < kmax; k4 += 4) {
        float4 q0 = LD4(w1 + c0*ld + k4);
        float4 q1 = LD4(w1 + c1*ld + k4);
        float4 q2 = LD4(w2 + c0*ld + k4);
        float4 q3 = LD4(w2 + c1*ld + k4);
        float w10[4] = {q0.x, q0.y, q0.z, q0.w};
        float w11[4] = {q1.x, q1.y, q1.z, q1.w};
        float w20[4] = {q2.x, q2.y, q2.z, q2.w};
        float w21[4] = {q3.x, q3.y, q3.z, q3.w};
        #pragma unroll
        for (int u = 0; u < 4; ++u) {
            float v0 = sT[(k4+u)*33 + r0];
            float v1 = sT[(k4+u)*33 + r1];
            a00 = fmaf(v0, w10[u], a00); a01 = fmaf(v0, w11[u], a01);
            a10 = fmaf(v1, w10[u], a10); a11 = fmaf(v1, w11[u], a11);
            b00 = fmaf(v0, w20[u], b00); b01 = fmaf(v0, w21[u], b01);
            b10 = fmaf(v1, w20[u], b10); b11 = fmaf(v1, w21[u], b11);
        }
    }
}

// single-gate GEMM segment
__device__ __forceinline__ void seg1(
    const float* __restrict__ w1, int ld, int kmax,
    int c0, int c1, const float* __restrict__ sT, int r0, int r1,
    float& a00, float& a01, float& a10, float& a11)
{
    for (int k4 = 0; k4 < kmax; k4 += 4) {
        float4 q0 = LD4(w1 + c0*ld + k4);
        float4 q1 = LD4(w1 + c1*ld + k4);
        float w10[4] = {q0.x, q0.y, q0.z, q0.w};
        float w11[4] = {q1.x, q1.y, q1.z, q1.w};
        #pragma unroll
        for (int u = 0; u < 4; ++u) {
            float v0 = sT[(k4+u)*33 + r0];
            float v1 = sT[(k4+u)*33 + r1];
            a00 = fmaf(v0, w10[u], a00); a01 = fmaf(v0, w11[u], a01);
            a10 = fmaf(v1, w10[u], a10); a11 = fmaf(v1, w11[u], a11);
        }
    }
}

// ---------------- prologue: transpose input to [t][b][i] --------------------
__global__ void transpose_in_kernel(const float* __restrict__ inp) {
    // one block per (b, c) pair
    int b = blockIdx.x / 3, c = blockIdx.x % 3;
    float* dst = (c == 0) ? g_xt : (c == 1) ? g_mt : g_dt;
    const float* src = inp + ((size_t)b*3 + c) * IN_DIM * T_DIM;
    __shared__ float s[IN_DIM * 50];
    int tid = threadIdx.x;
    for (int chunk = 0; chunk < 4; ++chunk) {
        int t0 = chunk * 50;
        for (int idx = tid; idx < IN_DIM*50; idx += NTHR) {
            int i = idx / 50, tt = idx % 50;
            s[i*50 + tt] = src[i*T_DIM + t0 + tt];
        }
        __syncthreads();
        for (int idx = tid; idx < IN_DIM*50; idx += NTHR) {
            int tt = idx / IN_DIM, i = idx % IN_DIM;
            dst[((size_t)(t0+tt)*B_DIM + b)*IN_DIM + i] = s[i*50 + tt];
        }
        __syncthreads();
    }
}

// ---------------- prologue: mask passthrough -------------------------------
__global__ void mask_copy_kernel(const float* __restrict__ inp, float* __restrict__ out) {
    int idx = blockIdx.x * blockDim.x + threadIdx.x;
    if (idx < B_DIM*IN_DIM*T_DIM) {
        int b = idx / (IN_DIM*T_DIM);
        int r = idx - b * (IN_DIM*T_DIM);
        out[M_OFF + idx] = inp[((size_t)b*3 + 1)*(IN_DIM*T_DIM) + r];
    }
}

// ---------------- persistent GRU-D kernel ----------------------------------
extern "C" __global__ void __launch_bounds__(NTHR)
grud_persistent(
    const float* __restrict__ x_mean,
    const float* __restrict__ w_dg_x, const float* __restrict__ b_dg_x,
    const float* __restrict__ w_dg_h, const float* __restrict__ b_dg_h,
    const float* __restrict__ w_xz, const float* __restrict__ w_hz,
    const float* __restrict__ w_mz, const float* __restrict__ b_z,
    const float* __restrict__ w_xr, const float* __restrict__ w_hr,
    const float* __restrict__ w_mr, const float* __restrict__ b_r,
    const float* __restrict__ w_xh, const float* __restrict__ w_hh,
    const float* __restrict__ w_mh, const float* __restrict__ b_h,
    const float* __restrict__ w_hy, const float* __restrict__ b_hy,
    const float* __restrict__ bn_gamma, const float* __restrict__ bn_beta,
    float* __restrict__ out)
{
    extern __shared__ float smem[];
    float* wdgxT  = smem;                    // 64*64   (transposed [k][i])
    float* wdghT  = wdgxT + 64*64;           // 64*256  (transposed [k][j])
    float* xsT    = wdghT + 64*256;          // 64*33
    float* msT    = xsT + 64*33;             // 64*33
    float* hgT    = msT + 64*33;             // 256*33  (reused as rhT in 2b)
    float* sd     = hgT + 256*33;            // 4*64
    float* sx     = sd + 256;                // 4*64
    float* smk    = sx + 256;                // 4*64
    float* sxmean = smk + 256;               // 64
    float* sred   = sxmean + 64;             // 64
    float* sbn    = sred + 64;               // 64

    const int tid = threadIdx.x;
    const int blk = blockIdx.x;

    // persistent smem weights (transposed for conflict-free LDS)
    for (int idx = tid; idx < 64*64; idx += NTHR) {
        int i = idx >> 6, k = idx & 63;
        wdgxT[k*64 + i] = w_dg_x[idx];
    }
    for (int idx = tid; idx < 256*64; idx += NTHR) {
        int j = idx >> 6, k = idx & 63;
        wdghT[k*256 + j] = w_dg_h[idx];
    }
    if (tid < 64) sxmean[tid] = x_mean[tid];
    __syncthreads();

    // phase-1 per-thread constants (j = tid)
    const float gam  = bn_gamma[tid];
    const float bet  = bn_beta[tid];
    const float why0 = w_hy[tid];
    const float why1 = w_hy[H_DIM + tid];
    const float bhy0 = b_hy[0], bhy1 = b_hy[1];
    const float bdgh = b_dg_h[tid];
    const int   p1r  = tid >> 6;     // 0..3 (row within CTA's 4-row group)
    const int   p1i  = tid & 63;     // 0..63
    const float bdgx = b_dg_x[p1i];
    const int   b0   = blk * 4;

    // phase-2 tile mapping
    const int bt = blk >> 3, jt = blk & 7;
    const int bbase = bt * 32, j0 = jt * 32;
    const int ty = tid >> 4, tx = tid & 15;
    const int rr0 = ty, rr1 = ty + 16;
    const int cc0 = tx, cc1 = tx + 16;
    const int jc0 = j0 + cc0, jc1 = j0 + cc1;

    for (int t = 0; t <= T_DIM; ++t) {
        // ================= PHASE 1 =================
        if (t > 0) {
            const int p = (t - 1) & 1;
            float mu  = __ldcg(&g_bnsum[p][tid]) * (1.0f / B_DIM);
            float var = __ldcg(&g_bnsq[p][tid]) * (1.0f / B_DIM) - mu*mu;
            float rstd = rsqrtf(var + BN_EPS);
            for (int r = 0; r < 4; ++r) {
                int b = b0 + r;
                float hn = __ldcg(&g_hnew[b*H_DIM + tid]);
                float hb = (hn - mu) * rstd * gam + bet;
                g_h[b*H_DIM + tid] = hb;
                out[HID_OFF + ((size_t)b*T_DIM + (t-1))*H_DIM + tid] = hb;
                float p0 = hb * why0, p1 = hb * why1;
                #pragma unroll
                for (int o = 16; o > 0; o >>= 1) {
                    p0 += __shfl_down_sync(0xffffffffu, p0, o);
                    p1 += __shfl_down_sync(0xffffffffu, p1, o);
                }
                if ((tid & 31) == 0) { sred[tid >> 5] = p0; sred[8 + (tid >> 5)] = p1; }
                __syncthreads();
                if (tid == 0) {
                    float s0 = 0.f, s1 = 0.f;
                    #pragma unroll
                    for (int w = 0; w < 8; ++w) { s0 += sred[w]; s1 += sred[8 + w]; }
                    out[Y_OFF + ((size_t)b*T_DIM + (t-1))*O_DIM + 0] = sigm(s0 + bhy0);
                    out[Y_OFF + ((size_t)b*T_DIM + (t-1))*O_DIM + 1] = sigm(s1 + bhy1);
                }
                __syncthreads();
            }
        }
        if (t == T_DIM) break;

        if (blk == 0) { g_bnsum[t & 1][tid] = 0.0f; g_bnsq[t & 1][tid] = 0.0f; }

        // load this CTA's 4 rows of x/m/d (contiguous 256 floats)
        {
            const size_t base = ((size_t)t*B_DIM + b0) * IN_DIM;
            sx[tid]  = g_xt[base + tid];
            smk[tid] = g_mt[base + tid];
            sd[tid]  = g_dt[base + tid];
        }
        __syncthreads();

        // gamma_x + x_imp  (thread = (p1r, p1i))
        {
            float acc = bdgx;
            const float* dr = sd + p1r*64;
            #pragma unroll 8
            for (int k = 0; k < 64; ++k) acc = fmaf(dr[k], wdgxT[k*64 + p1i], acc);
            float gx = expf(-fmaxf(acc, 0.0f));
            int b = b0 + p1r;
            float xv = sx[tid], mv = smk[tid];
            float xl = (t == 0) ? 0.0f : g_xlast[b*IN_DIM + p1i];
            xl = (mv > 0.0f) ? xv : xl;
            g_xlast[b*IN_DIM + p1i] = xl;
            float xi = mv * xv + (1.0f - mv) * (gx * xl + (1.0f - gx) * sxmean[p1i]);
            g_ximp[b*IN_DIM + p1i] = xi;
            out[X_OFF + ((size_t)b*IN_DIM + p1i)*T_DIM + t] = xi;
        }
        // gamma_h + hg (thread j = tid, 4 rows)
        for (int r = 0; r < 4; ++r) {
            int b = b0 + r;
            float acc = bdgh;
            const float* dr = sd + r*64;
            #pragma unroll 8
            for (int k = 0; k < 64; ++k) acc = fmaf(dr[k], wdghT[k*256 + tid], acc);
            float gh = expf(-fmaxf(acc, 0.0f));
            float hv = (t == 0) ? 0.0f : g_h[b*H_DIM + tid];
            g_hg[b*H_DIM + tid] = gh * hv;
        }
        grid_sync();

        // ================= PHASE 2a : z, r =================
        for (int idx = tid; idx < 32*64; idx += NTHR) {
            int row = idx >> 6, k = idx & 63;
            xsT[k*33 + row] = __ldcg(&g_ximp[(bbase + row)*IN_DIM + k]);
            msT[k*33 + row] = g_mt[((size_t)t*B_DIM + bbase + row)*IN_DIM + k];
        }
        for (int idx = tid; idx < 32*256; idx += NTHR) {
            int row = idx >> 8, k = idx & 255;
            hgT[k*33 + row] = __ldcg(&g_hg[(bbase + row)*H_DIM + k]);
        }
        __syncthreads();

        float az00=0,az01=0,az10=0,az11=0, ar00=0,ar01=0,ar10=0,ar11=0;
        seg2(w_xz, w_xr, 64, 64,  jc0, jc1, xsT, rr0, rr1, az00,az01,az10,az11, ar00,ar01,ar10,ar11);
        seg2(w_mz, w_mr, 64, 64,  jc0, jc1, msT, rr0, rr1, az00,az01,az10,az11, ar00,ar01,ar10,ar11);
        seg2(w_hz, w_hr, 256, 256, jc0, jc1, hgT, rr0, rr1, az00,az01,az10,az11, ar00,ar01,ar10,ar11);

        float bz0 = b_z[jc0], bz1 = b_z[jc1], br0 = b_r[jc0], br1 = b_r[jc1];
        float z00 = sigm(az00 + bz0), z01 = sigm(az01 + bz1);
        float z10 = sigm(az10 + bz0), z11 = sigm(az11 + bz1);
        float r00 = sigm(ar00 + br0), r01 = sigm(ar01 + br1);
        float r10 = sigm(ar10 + br0), r11 = sigm(ar11 + br1);
        float hg00 = hgT[jc0*33 + rr0], hg01 = hgT[jc1*33 + rr0];
        float hg10 = hgT[jc0*33 + rr1], hg11 = hgT[jc1*33 + rr1];
        g_rh[(bbase + rr0)*H_DIM + jc0] = r00 * hg00;
        g_rh[(bbase + rr0)*H_DIM + jc1] = r01 * hg01;
        g_rh[(bbase + rr1)*H_DIM + jc0] = r10 * hg10;
        g_rh[(bbase + rr1)*H_DIM + jc1] = r11 * hg11;
        grid_sync();

        // ================= PHASE 2b : h_tilde, h_new, BN sums =================
        for (int idx = tid; idx < 32*256; idx += NTHR) {
            int row = idx >> 8, k = idx & 255;
            hgT[k*33 + row] = __ldcg(&g_rh[(bbase + row)*H_DIM + k]);
        }
        if (tid < 64) sbn[tid] = 0.0f;
        __syncthreads();

        float ah00=0,ah01=0,ah10=0,ah11=0;
        seg1(w_xh, 64, 64,  jc0, jc1, xsT, rr0, rr1, ah00,ah01,ah10,ah11);
        seg1(w_mh, 64, 64,  jc0, jc1, msT, rr0, rr1, ah00,ah01,ah10,ah11);
        seg1(w_hh, 256, 256, jc0, jc1, hgT, rr0, rr1, ah00,ah01,ah10,ah11);

        float bh0 = b_h[jc0], bh1 = b_h[jc1];
        float ht00 = tanhf(ah00 + bh0), ht01 = tanhf(ah01 + bh1);
        float ht10 = tanhf(ah10 + bh0), ht11 = tanhf(ah11 + bh1);
        float hn00 = (1.0f - z00)*hg00 + z00*ht00;
        float hn01 = (1.0f - z01)*hg01 + z01*ht01;
        float hn10 = (1.0f - z10)*hg10 + z10*ht10;
        float hn11 = (1.0f - z11)*hg11 + z11*ht11;
        g_hnew[(bbase + rr0)*H_DIM + jc0] = hn00;
        g_hnew[(bbase + rr0)*H_DIM + jc1] = hn01;
        g_hnew[(bbase + rr1)*H_DIM + jc0] = hn10;
        g_hnew[(bbase + rr1)*H_DIM + jc1] = hn11;
        atomicAdd(&sbn[cc0],      hn00 + hn10);
        atomicAdd(&sbn[cc1],      hn01 + hn11);
        atomicAdd(&sbn[32 + cc0], hn00*hn00 + hn10*hn10);
        atomicAdd(&sbn[32 + cc1], hn01*hn01 + hn11*hn11);
        __syncthreads();
        if (tid < 32) {
            atomicAdd(&g_bnsum[t & 1][j0 + tid], sbn[tid]);
            atomicAdd(&g_bnsq[t & 1][j0 + tid],  sbn[32 + tid]);
        }
        grid_sync();
    }
}

// ---------------- host launcher --------------------------------------------
extern "C" void kernel_launch(void* const* d_in, const int* in_sizes, int n_in,
                              void* d_out, int out_size) {
    (void)in_sizes; (void)n_in; (void)out_size;
    const float* inp     = (const float*)d_in[0];
    const float* x_mean  = (const float*)d_in[1];
    const float* w_dg_x  = (const float*)d_in[2];
    const float* b_dg_x  = (const float*)d_in[3];
    const float* w_dg_h  = (const float*)d_in[4];
    const float* b_dg_h  = (const float*)d_in[5];
    const float* w_xz    = (const float*)d_in[6];
    const float* w_hz    = (const float*)d_in[7];
    const float* w_mz    = (const float*)d_in[8];
    const float* b_z     = (const float*)d_in[9];
    const float* w_xr    = (const float*)d_in[10];
    const float* w_hr    = (const float*)d_in[11];
    const float* w_mr    = (const float*)d_in[12];
    const float* b_r     = (const float*)d_in[13];
    const float* w_xh    = (const float*)d_in[14];
    const float* w_hh    = (const float*)d_in[15];
    const float* w_mh    = (const float*)d_in[16];
    const float* b_h     = (const float*)d_in[17];
    const float* w_hy    = (const float*)d_in[18];
    const float* b_hy    = (const float*)d_in[19];
    const float* bn_g    = (const float*)d_in[20];
    const float* bn_b    = (const float*)d_in[21];
    float* out = (float*)d_out;

    // dynamic smem for the persistent kernel
    const int SMEM_FLOATS = 64*64 + 64*256 + 64*33 + 64*33 + 256*33
                          + 256 + 256 + 256 + 64 + 64 + 64;
    const int SMEM_BYTES = SMEM_FLOATS * 4;
    cudaFuncSetAttribute(grud_persistent,
                         cudaFuncAttributeMaxDynamicSharedMemorySize, SMEM_BYTES);

    transpose_in_kernel<<<B_DIM*3, NTHR>>>(inp);
    mask_copy_kernel<<<(B_DIM*IN_DIM*T_DIM + NTHR - 1)/NTHR, NTHR>>>(inp, out);
    grud_persistent<<<NBLK, NTHR, SMEM_BYTES>>>(
        x_mean, w_dg_x, b_dg_x, w_dg_h, b_dg_h,
        w_xz, w_hz, w_mz, b_z,
        w_xr, w_hr, w_mr, b_r,
        w_xh, w_hh, w_mh, b_h,
        w_hy, b_hy, bn_g, bn_b, out);
}

// round 3
// speedup vs baseline: 3.5242x; 3.5242x over previous
#include <cuda_runtime.h>
#include <math.h>

#define B_DIM  512
#define IN_DIM 64
#define H_DIM  256
#define T_DIM  200
#define O_DIM  2
#define NBLK   128
#define NTHR   256
#define BN_EPS 1e-5f

// output region offsets (floats)
#define Y_OFF   0
#define HID_OFF (B_DIM*T_DIM*O_DIM)
#define X_OFF   (HID_OFF + B_DIM*T_DIM*H_DIM)
#define M_OFF   (X_OFF + B_DIM*IN_DIM*T_DIM)

#define WS64  68
#define WS256 260
#define ACT_S 388

// ---------------- device scratch ----------------
__device__ float g_xt[T_DIM*B_DIM*IN_DIM];   // [t][b][i]
__device__ float g_mt[T_DIM*B_DIM*IN_DIM];
__device__ float g_dt[T_DIM*B_DIM*IN_DIM];
__device__ float g_xs[T_DIM*B_DIM*IN_DIM];   // x_imp history [t][b][i]
__device__ float g_hg[B_DIM*H_DIM];          // gamma_h * h_norm
__device__ float g_rh[B_DIM*H_DIM];          // r * hg
__device__ float g_ximp[B_DIM*IN_DIM];
__device__ float g_bnsum[2][H_DIM];
__device__ float g_bnsq[2][H_DIM];
__device__ unsigned int g_bar_count;
__device__ unsigned int g_bar_gen;

// ---------------- grid barrier ----------------
__device__ __forceinline__ void grid_sync() {
    __syncthreads();
    if (threadIdx.x == 0) {
        volatile unsigned int* genp = (volatile unsigned int*)&g_bar_gen;
        unsigned int gen = *genp;
        __threadfence();
        if (atomicAdd(&g_bar_count, 1u) == (unsigned)(NBLK - 1)) {
            g_bar_count = 0u;
            __threadfence();
            *genp = gen + 1u;
        } else {
            while (*genp == gen) { __nanosleep(20); }
        }
        __threadfence();
    }
    __syncthreads();
}

__device__ __forceinline__ float sigm(float v) { return 1.0f / (1.0f + expf(-v)); }

// 2x2 register-tile GEMM segment, smem activations (row ptrs) x smem weights (col ptrs)
template<int K>
__device__ __forceinline__ void gseg(
    const float* __restrict__ a0, const float* __restrict__ a1,
    const float* __restrict__ w0, const float* __restrict__ w1,
    float& c00, float& c01, float& c10, float& c11)
{
#pragma unroll 8
    for (int k = 0; k < K; k += 4) {
        float4 av0 = *(const float4*)(a0 + k);
        float4 av1 = *(const float4*)(a1 + k);
        float4 wv0 = *(const float4*)(w0 + k);
        float4 wv1 = *(const float4*)(w1 + k);
        c00 = fmaf(av0.x, wv0.x, c00); c01 = fmaf(av0.x, wv1.x, c01);
        c10 = fmaf(av1.x, wv0.x, c10); c11 = fmaf(av1.x, wv1.x, c11);
        c00 = fmaf(av0.y, wv0.y, c00); c01 = fmaf(av0.y, wv1.y, c01);
        c10 = fmaf(av1.y, wv0.y, c10); c11 = fmaf(av1.y, wv1.y, c11);
        c00 = fmaf(av0.z, wv0.z, c00); c01 = fmaf(av0.z, wv1.z, c01);
        c10 = fmaf(av1.z, wv0.z, c10); c11 = fmaf(av1.z, wv1.z, c11);
        c00 = fmaf(av0.w, wv0.w, c00); c01 = fmaf(av0.w, wv1.w, c01);
        c10 = fmaf(av1.w, wv0.w, c10); c11 = fmaf(av1.w, wv1.w, c11);
    }
}

// ---------------- prologue: transpose input to [t][b][i] ----------------
__global__ void transpose_in_kernel(const float* __restrict__ inp) {
    int b = blockIdx.x / 3, c = blockIdx.x % 3;
    float* dst = (c == 0) ? g_xt : (c == 1) ? g_mt : g_dt;
    const float* src = inp + ((size_t)b*3 + c) * IN_DIM * T_DIM;
    __shared__ float s[IN_DIM * 50];
    int tid = threadIdx.x;
    for (int chunk = 0; chunk < 4; ++chunk) {
        int t0 = chunk * 50;
        for (int idx = tid; idx < IN_DIM*50; idx += NTHR) {
            int i = idx / 50, tt = idx % 50;
            s[i*50 + tt] = src[i*T_DIM + t0 + tt];
        }
        __syncthreads();
        for (int idx = tid; idx < IN_DIM*50; idx += NTHR) {
            int tt = idx / IN_DIM, i = idx % IN_DIM;
            dst[((size_t)(t0+tt)*B_DIM + b)*IN_DIM + i] = s[i*50 + tt];
        }
        __syncthreads();
    }
}

__global__ void mask_copy_kernel(const float* __restrict__ inp, float* __restrict__ out) {
    int idx = blockIdx.x * blockDim.x + threadIdx.x;
    if (idx < B_DIM*IN_DIM*T_DIM) {
        int b = idx / (IN_DIM*T_DIM);
        int r = idx - b * (IN_DIM*T_DIM);
        out[M_OFF + idx] = inp[((size_t)b*3 + 1)*(IN_DIM*T_DIM) + r];
    }
}

// ---------------- epilogue: x_imp transpose [t][b*64+i] -> [b*64+i][t] ----------------
__global__ void x_transpose_kernel(float* __restrict__ out) {
    __shared__ float tile[32][33];
    int bi0 = blockIdx.x * 32;
    int t0  = blockIdx.y * 32;
    int tx = threadIdx.x & 31, ty = threadIdx.x >> 5;   // 256 thr: ty 0..7
    for (int i = ty; i < 32; i += 8) {
        int t = t0 + i;
        if (t < T_DIM) tile[i][tx] = g_xs[(size_t)t*(B_DIM*IN_DIM) + bi0 + tx];
    }
    __syncthreads();
    for (int i = ty; i < 32; i += 8) {
        int t = t0 + tx;
        if (t < T_DIM) out[X_OFF + (size_t)(bi0+i)*T_DIM + t] = tile[tx][i];
    }
}

// ---------------- epilogue: y = sigmoid(hidden @ w_hy.T + b_hy) ----------------
__global__ void y_epilogue(const float* __restrict__ w_hy, const float* __restrict__ b_hy,
                           float* __restrict__ out) {
    __shared__ float wz[2*H_DIM];
    int tid = threadIdx.x;
    for (int i = tid; i < 2*H_DIM; i += NTHR) wz[i] = w_hy[i];
    __syncthreads();
    float bh0 = b_hy[0], bh1 = b_hy[1];
    int lane = tid & 31;
    int warp = (blockIdx.x * NTHR + tid) >> 5;
    int nw   = (gridDim.x * NTHR) >> 5;
    const float* hid = out + HID_OFF;
    for (int p = warp; p < B_DIM*T_DIM; p += nw) {
        const float* h = hid + (size_t)p*H_DIM;
        float s0 = 0.f, s1 = 0.f;
        #pragma unroll
        for (int q = 0; q < 2; ++q) {
            int kb = lane*8 + q*4;
            float4 hv = *(const float4*)(h + kb);
            s0 += hv.x*wz[kb] + hv.y*wz[kb+1] + hv.z*wz[kb+2] + hv.w*wz[kb+3];
            s1 += hv.x*wz[H_DIM+kb] + hv.y*wz[H_DIM+kb+1] + hv.z*wz[H_DIM+kb+2] + hv.w*wz[H_DIM+kb+3];
        }
        #pragma unroll
        for (int o = 16; o > 0; o >>= 1) {
            s0 += __shfl_down_sync(0xffffffffu, s0, o);
            s1 += __shfl_down_sync(0xffffffffu, s1, o);
        }
        if (lane == 0) {
            out[Y_OFF + (size_t)p*O_DIM + 0] = sigm(s0 + bh0);
            out[Y_OFF + (size_t)p*O_DIM + 1] = sigm(s1 + bh1);
        }
    }
}

// ---------------- persistent GRU-D kernel ----------------
extern "C" __global__ void __launch_bounds__(NTHR)
grud_persistent(
    const float* __restrict__ x_mean,
    const float* __restrict__ w_dg_x, const float* __restrict__ b_dg_x,
    const float* __restrict__ w_dg_h, const float* __restrict__ b_dg_h,
    const float* __restrict__ w_xz, const float* __restrict__ w_hz,
    const float* __restrict__ w_mz, const float* __restrict__ b_z,
    const float* __restrict__ w_xr, const float* __restrict__ w_hr,
    const float* __restrict__ w_mr, const float* __restrict__ b_r,
    const float* __restrict__ w_xh, const float* __restrict__ w_hh,
    const float* __restrict__ w_mh, const float* __restrict__ b_h,
    const float* __restrict__ bn_gamma, const float* __restrict__ bn_beta,
    float* __restrict__ out)
{
    extern __shared__ float smem[];
    float* s_wzx = smem;                         // 32*68
    float* s_wrx = s_wzx + 32*WS64;
    float* s_whx = s_wrx + 32*WS64;
    float* s_wzm = s_whx + 32*WS64;
    float* s_wrm = s_wzm + 32*WS64;
    float* s_whm = s_wrm + 32*WS64;
    float* s_wzh = s_whm + 32*WS64;              // 32*260
    float* s_wrh = s_wzh + 32*WS256;
    float* s_whh = s_wrh + 32*WS256;
    float* s_wdgh = s_whh + 32*WS256;            // 32*68
    float* s_wdgx = s_wdgh + 32*WS64;            // 32*68
    float* s_act  = s_wdgx + 32*WS64;            // 32*388 (dd aliases front)
    float* s_bn   = s_act + 32*ACT_S;            // 64
    float* s_dd   = s_act;                       // 32*68 alias (phase-1 only)

    const int tid = threadIdx.x;
    const int blk = blockIdx.x;
    const int bt = blk >> 3, jt = blk & 7;
    const int b0 = bt * 32, j0 = jt * 32;
    const int ty = tid >> 4, tx = tid & 15;
    const int rl0 = ty, rl1 = ty + 16;
    const int cl0 = tx, cl1 = tx + 16;
    const int jc0 = j0 + cl0, jc1 = j0 + cl1;

    // ---- one-time weight staging ----
    {
        const float* srcs64[8] = { w_xz, w_xr, w_xh, w_mz, w_mr, w_mh, w_dg_h, w_dg_x };
        float* dsts64[8] = { s_wzx, s_wrx, s_whx, s_wzm, s_wrm, s_whm, s_wdgh, s_wdgx };
        for (int a = 0; a < 8; ++a) {
            int row0 = (a == 7) ? ((jt < 2) ? jt*32 : 0) : j0;
            const float* s = srcs64[a];
            float* d = dsts64[a];
            for (int idx = tid; idx < 32*64; idx += NTHR) {
                int c = idx >> 6, k = idx & 63;
                d[c*WS64 + k] = s[(row0 + c)*64 + k];
            }
        }
        for (int idx = tid; idx < 32*256; idx += NTHR) {
            int c = idx >> 8, k = idx & 255;
            s_wzh[c*WS256 + k] = w_hz[(j0 + c)*256 + k];
            s_wrh[c*WS256 + k] = w_hr[(j0 + c)*256 + k];
            s_whh[c*WS256 + k] = w_hh[(j0 + c)*256 + k];
        }
    }
    __syncthreads();

    // ---- per-thread constants ----
    const float gam0 = bn_gamma[jc0], gam1 = bn_gamma[jc1];
    const float bet0 = bn_beta[jc0],  bet1 = bn_beta[jc1];
    const float bz0 = b_z[jc0], bz1 = b_z[jc1];
    const float br0 = b_r[jc0], br1 = b_r[jc1];
    const float bh0 = b_h[jc0], bh1 = b_h[jc1];
    const float bdgh0 = b_dg_h[jc0], bdgh1 = b_dg_h[jc1];
    const int ic0 = ((jt < 2) ? jt*32 : 0) + cl0;
    const int ic1 = ((jt < 2) ? jt*32 : 0) + cl1;
    const float bdgx0 = b_dg_x[ic0], bdgx1 = b_dg_x[ic1];
    const float xm0 = x_mean[ic0], xm1 = x_mean[ic1];

    // register-resident state
    float hp00 = 0.f, hp01 = 0.f, hp10 = 0.f, hp11 = 0.f;   // pre-BN h_new
    float xl00 = 0.f, xl01 = 0.f, xl10 = 0.f, xl11 = 0.f;   // x_last (jt<2)

    for (int t = 0; t <= T_DIM; ++t) {
        // ---------- PHASE 1: BN normalize (regs), hidden out, gamma_h, hg, x_imp ----------
        float hn00, hn01, hn10, hn11;
        if (t > 0) {
            const int p = (t - 1) & 1;
            float mu0 = __ldcg(&g_bnsum[p][jc0]) * (1.0f / B_DIM);
            float mu1 = __ldcg(&g_bnsum[p][jc1]) * (1.0f / B_DIM);
            float rs0 = rsqrtf(__ldcg(&g_bnsq[p][jc0]) * (1.0f / B_DIM) - mu0*mu0 + BN_EPS);
            float rs1 = rsqrtf(__ldcg(&g_bnsq[p][jc1]) * (1.0f / B_DIM) - mu1*mu1 + BN_EPS);
            hn00 = (hp00 - mu0) * rs0 * gam0 + bet0;
            hn01 = (hp01 - mu1) * rs1 * gam1 + bet1;
            hn10 = (hp10 - mu0) * rs0 * gam0 + bet0;
            hn11 = (hp11 - mu1) * rs1 * gam1 + bet1;
            size_t ho0 = HID_OFF + ((size_t)(b0+rl0)*T_DIM + (t-1)) * H_DIM;
            size_t ho1 = HID_OFF + ((size_t)(b0+rl1)*T_DIM + (t-1)) * H_DIM;
            out[ho0 + jc0] = hn00; out[ho0 + jc1] = hn01;
            out[ho1 + jc0] = hn10; out[ho1 + jc1] = hn11;
        } else {
            hn00 = hn01 = hn10 = hn11 = 0.f;
        }
        if (t == T_DIM) break;

        if (bt == 0 && tid < 32) {
            g_bnsum[t & 1][j0 + tid] = 0.f;
            g_bnsq [t & 1][j0 + tid] = 0.f;
        }

        // stage d tile (32 x 64)
        {
            const float* src = g_dt + ((size_t)t*B_DIM + b0) * IN_DIM;
            for (int idx = tid; idx < 512; idx += NTHR) {
                int row = idx >> 4, k4 = (idx & 15) << 2;
                *(float4*)&s_dd[row*WS64 + k4] = __ldcg((const float4*)(src + row*64 + k4));
            }
        }
        __syncthreads();

        // gamma_h GEMM (k=64) + hg
        {
            float g00 = 0.f, g01 = 0.f, g10 = 0.f, g11 = 0.f;
            gseg<64>(s_dd + rl0*WS64, s_dd + rl1*WS64,
                     s_wdgh + cl0*WS64, s_wdgh + cl1*WS64, g00, g01, g10, g11);
            float gh00 = expf(-fmaxf(g00 + bdgh0, 0.f));
            float gh01 = expf(-fmaxf(g01 + bdgh1, 0.f));
            float gh10 = expf(-fmaxf(g10 + bdgh0, 0.f));
            float gh11 = expf(-fmaxf(g11 + bdgh1, 0.f));
            g_hg[(b0+rl0)*H_DIM + jc0] = gh00 * hn00;
            g_hg[(b0+rl0)*H_DIM + jc1] = gh01 * hn01;
            g_hg[(b0+rl1)*H_DIM + jc0] = gh10 * hn10;
            g_hg[(b0+rl1)*H_DIM + jc1] = gh11 * hn11;
        }

        // gamma_x + x_imp (jt 0,1 cover the 64 input dims)
        if (jt < 2) {
            float g00 = 0.f, g01 = 0.f, g10 = 0.f, g11 = 0.f;
            gseg<64>(s_dd + rl0*WS64, s_dd + rl1*WS64,
                     s_wdgx + cl0*WS64, s_wdgx + cl1*WS64, g00, g01, g10, g11);
            float gx00 = expf(-fmaxf(g00 + bdgx0, 0.f));
            float gx01 = expf(-fmaxf(g01 + bdgx1, 0.f));
            float gx10 = expf(-fmaxf(g10 + bdgx0, 0.f));
            float gx11 = expf(-fmaxf(g11 + bdgx1, 0.f));
            size_t xb0 = ((size_t)t*B_DIM + b0 + rl0) * IN_DIM;
            size_t xb1 = ((size_t)t*B_DIM + b0 + rl1) * IN_DIM;
            float x00 = __ldcg(&g_xt[xb0 + ic0]), x01 = __ldcg(&g_xt[xb0 + ic1]);
            float x10 = __ldcg(&g_xt[xb1 + ic0]), x11 = __ldcg(&g_xt[xb1 + ic1]);
            float m00 = __ldcg(&g_mt[xb0 + ic0]), m01 = __ldcg(&g_mt[xb0 + ic1]);
            float m10 = __ldcg(&g_mt[xb1 + ic0]), m11 = __ldcg(&g_mt[xb1 + ic1]);
            xl00 = (m00 > 0.f) ? x00 : xl00;  xl01 = (m01 > 0.f) ? x01 : xl01;
            xl10 = (m10 > 0.f) ? x10 : xl10;  xl11 = (m11 > 0.f) ? x11 : xl11;
            float xi00 = m00*x00 + (1.f-m00)*(gx00*xl00 + (1.f-gx00)*xm0);
            float xi01 = m01*x01 + (1.f-m01)*(gx01*xl01 + (1.f-gx01)*xm1);
            float xi10 = m10*x10 + (1.f-m10)*(gx10*xl10 + (1.f-gx10)*xm0);
            float xi11 = m11*x11 + (1.f-m11)*(gx11*xl11 + (1.f-gx11)*xm1);
            g_ximp[(b0+rl0)*IN_DIM + ic0] = xi00;  g_ximp[(b0+rl0)*IN_DIM + ic1] = xi01;
            g_ximp[(b0+rl1)*IN_DIM + ic0] = xi10;  g_ximp[(b0+rl1)*IN_DIM + ic1] = xi11;
            g_xs[xb0 + ic0] = xi00;  g_xs[xb0 + ic1] = xi01;
            g_xs[xb1 + ic0] = xi10;  g_xs[xb1 + ic1] = xi11;
        }
        grid_sync();

        // ---------- PHASE 2a: z, r ----------
        {
            const float* msrc = g_mt + ((size_t)t*B_DIM + b0) * IN_DIM;
            for (int idx = tid; idx < 512; idx += NTHR) {
                int row = idx >> 4, k4 = (idx & 15) << 2;
                *(float4*)&s_act[row*ACT_S + k4] =
                    __ldcg((const float4*)(g_ximp + (b0+row)*IN_DIM + k4));
                *(float4*)&s_act[row*ACT_S + 64 + k4] =
                    __ldcg((const float4*)(msrc + row*64 + k4));
            }
            for (int idx = tid; idx < 2048; idx += NTHR) {
                int row = idx >> 6, k4 = (idx & 63) << 2;
                *(float4*)&s_act[row*ACT_S + 128 + k4] =
                    __ldcg((const float4*)(g_hg + (b0+row)*H_DIM + k4));
            }
        }
        __syncthreads();

        const float* a0 = s_act + rl0*ACT_S;
        const float* a1 = s_act + rl1*ACT_S;

        float az00=0,az01=0,az10=0,az11=0, ar00=0,ar01=0,ar10=0,ar11=0;
        gseg<64> (a0,      a1,      s_wzx + cl0*WS64,  s_wzx + cl1*WS64,  az00,az01,az10,az11);
        gseg<64> (a0+64,   a1+64,   s_wzm + cl0*WS64,  s_wzm + cl1*WS64,  az00,az01,az10,az11);
        gseg<256>(a0+128,  a1+128,  s_wzh + cl0*WS256, s_wzh + cl1*WS256, az00,az01,az10,az11);
        gseg<64> (a0,      a1,      s_wrx + cl0*WS64,  s_wrx + cl1*WS64,  ar00,ar01,ar10,ar11);
        gseg<64> (a0+64,   a1+64,   s_wrm + cl0*WS64,  s_wrm + cl1*WS64,  ar00,ar01,ar10,ar11);
        gseg<256>(a0+128,  a1+128,  s_wrh + cl0*WS256, s_wrh + cl1*WS256, ar00,ar01,ar10,ar11);

        float z00 = sigm(az00 + bz0), z01 = sigm(az01 + bz1);
        float z10 = sigm(az10 + bz0), z11 = sigm(az11 + bz1);
        float r00 = sigm(ar00 + br0), r01 = sigm(ar01 + br1);
        float r10 = sigm(ar10 + br0), r11 = sigm(ar11 + br1);
        float hg00 = a0[128 + jc0], hg01 = a0[128 + jc1];
        float hg10 = a1[128 + jc0], hg11 = a1[128 + jc1];
        g_rh[(b0+rl0)*H_DIM + jc0] = r00 * hg00;
        g_rh[(b0+rl0)*H_DIM + jc1] = r01 * hg01;
        g_rh[(b0+rl1)*H_DIM + jc0] = r10 * hg10;
        g_rh[(b0+rl1)*H_DIM + jc1] = r11 * hg11;
        grid_sync();

        // ---------- PHASE 2b: h_tilde, h_new, BN sums ----------
        for (int idx = tid; idx < 2048; idx += NTHR) {
            int row = idx >> 6, k4 = (idx & 63) << 2;
            *(float4*)&s_act[row*ACT_S + 128 + k4] =
                __ldcg((const float4*)(g_rh + (b0+row)*H_DIM + k4));
        }
        if (tid < 64) s_bn[tid] = 0.f;
        __syncthreads();

        float ah00=0,ah01=0,ah10=0,ah11=0;
        gseg<64> (a0,     a1,     s_whx + cl0*WS64,  s_whx + cl1*WS64,  ah00,ah01,ah10,ah11);
        gseg<64> (a0+64,  a1+64,  s_whm + cl0*WS64,  s_whm + cl1*WS64,  ah00,ah01,ah10,ah11);
        gseg<256>(a0+128, a1+128, s_whh + cl0*WS256, s_whh + cl1*WS256, ah00,ah01,ah10,ah11);

        float ht00 = tanhf(ah00 + bh0), ht01 = tanhf(ah01 + bh1);
        float ht10 = tanhf(ah10 + bh0), ht11 = tanhf(ah11 + bh1);
        hp00 = (1.f - z00)*hg00 + z00*ht00;
        hp01 = (1.f - z01)*hg01 + z01*ht01;
        hp10 = (1.f - z10)*hg10 + z10*ht10;
        hp11 = (1.f - z11)*hg11 + z11*ht11;

        atomicAdd(&s_bn[cl0],      hp00 + hp10);
        atomicAdd(&s_bn[cl1],      hp01 + hp11);
        atomicAdd(&s_bn[32 + cl0], hp00*hp00 + hp10*hp10);
        atomicAdd(&s_bn[32 + cl1], hp01*hp01 + hp11*hp11);
        __syncthreads();
        if (tid < 32) {
            atomicAdd(&g_bnsum[t & 1][j0 + tid], s_bn[tid]);
            atomicAdd(&g_bnsq [t & 1][j0 + tid], s_bn[32 + tid]);
        }
        grid_sync();
    }
}

// ---------------- host launcher ----------------
extern "C" void kernel_launch(void* const* d_in, const int* in_sizes, int n_in,
                              void* d_out, int out_size) {
    (void)in_sizes; (void)n_in; (void)out_size;
    const float* inp     = (const float*)d_in[0];
    const float* x_mean  = (const float*)d_in[1];
    const float* w_dg_x  = (const float*)d_in[2];
    const float* b_dg_x  = (const float*)d_in[3];
    const float* w_dg_h  = (const float*)d_in[4];
    const float* b_dg_h  = (const float*)d_in[5];
    const float* w_xz    = (const float*)d_in[6];
    const float* w_hz    = (const float*)d_in[7];
    const float* w_mz    = (const float*)d_in[8];
    const float* b_z     = (const float*)d_in[9];
    const float* w_xr    = (const float*)d_in[10];
    const float* w_hr    = (const float*)d_in[11];
    const float* w_mr    = (const float*)d_in[12];
    const float* b_r     = (const float*)d_in[13];
    const float* w_xh    = (const float*)d_in[14];
    const float* w_hh    = (const float*)d_in[15];
    const float* w_mh    = (const float*)d_in[16];
    const float* b_h     = (const float*)d_in[17];
    const float* w_hy    = (const float*)d_in[18];
    const float* b_hy    = (const float*)d_in[19];
    const float* bn_g    = (const float*)d_in[20];
    const float* bn_b    = (const float*)d_in[21];
    float* out = (float*)d_out;

    const int SMEM_FLOATS = 6*32*WS64 + 3*32*WS256 + 2*32*WS64 + 32*ACT_S + 64;
    const int SMEM_BYTES = SMEM_FLOATS * 4;
    static int configured = 0;
    if (!configured) {
        cudaFuncSetAttribute(grud_persistent,
                             cudaFuncAttributeMaxDynamicSharedMemorySize, SMEM_BYTES);
        configured = 1;
    }

    transpose_in_kernel<<<B_DIM*3, NTHR>>>(inp);
    mask_copy_kernel<<<(B_DIM*IN_DIM*T_DIM + NTHR - 1)/NTHR, NTHR>>>(inp, out);
    grud_persistent<<<NBLK, NTHR, SMEM_BYTES>>>(
        x_mean, w_dg_x, b_dg_x, w_dg_h, b_dg_h,
        w_xz, w_hz, w_mz, b_z,
        w_xr, w_hr, w_mr, b_r,
        w_xh, w_hh, w_mh, b_h,
        bn_g, bn_b, out);
    x_transpose_kernel<<<dim3((B_DIM*IN_DIM)/32, (T_DIM+31)/32), NTHR>>>(out);
    y_epilogue<<<400, NTHR>>>(w_hy, b_hy, out);
}